// round 13
// baseline (speedup 1.0000x reference)
#include <cuda_runtime.h>
#include <math.h>

#define NN 10000
#define NE 160000

// ---------------- device scratch (no allocations allowed) ----------------
__device__ int   g_count;
__device__ int   g_ei[NE];
__device__ int   g_ej[NE];
__device__ float g_env[NE];
__device__ float g_ux[NE];
__device__ float g_uy[NE];
__device__ float g_uz[NE];
__device__ float g_rbf[NE * 20];
__device__ float g_h[NN * 128];
__device__ float g_phi[NN * 384];
__device__ float g_va[NN * 384];   // SoA: [node][coord][128]
__device__ float g_vb[NN * 384];   // SoA

__device__ __forceinline__ void red4(float* a, float x, float y, float z, float w) {
    asm volatile("red.global.add.v4.f32 [%0], {%1,%2,%3,%4};"
                 :: "l"(a), "f"(x), "f"(y), "f"(z), "f"(w) : "memory");
}

// ---------------- per-edge geometry + RBF precompute (with compaction) ----
__global__ void precompute_kernel(const float* __restrict__ xyz,
                                  const int* __restrict__ nbr) {
    int e = blockIdx.x * blockDim.x + threadIdx.x;
    bool active = false;
    int ni = 0, nj = 0;
    float rx = 0.f, ry = 0.f, rz = 0.f, dist = 1.f;
    if (e < NE) {
        ni = nbr[2 * e]; nj = nbr[2 * e + 1];
        float x0 = xyz[3 * ni], x1 = xyz[3 * ni + 1], x2 = xyz[3 * ni + 2];
        rx = xyz[3 * nj]     - x0;
        ry = xyz[3 * nj + 1] - x1;
        rz = xyz[3 * nj + 2] - x2;
        dist = sqrtf(rx * rx + ry * ry + rz * rz + 3e-15f);
        active = (dist < 5.0f);   // env==0 edges contribute nothing: drop them
    }
    unsigned mask = __ballot_sync(0xffffffffu, active);
    if (!active) return;
    int lane = threadIdx.x & 31;
    int rank = __popc(mask & ((1u << lane) - 1u));
    int leader = __ffs((int)mask) - 1;
    int base = 0;
    if (lane == leader) base = atomicAdd(&g_count, __popc(mask));
    base = __shfl_sync(mask, base, leader);
    int pos = base + rank;

    float inv = 1.0f / dist;
    g_ei[pos] = ni; g_ej[pos] = nj;
    g_ux[pos] = rx * inv;
    g_uy[pos] = ry * inv;
    g_uz[pos] = rz * inv;
    g_env[pos] = 0.5f * (cosf(dist * 0.6283185307179586f) + 1.0f);

    // rbf[k] = exp(-beta*(exp(-d)-mu_k)^2), mu_k linspace -> mult. recurrence
    const float MU0   = 0.006737946999085467f;   // exp(-5)
    const float DELTA = 0.05227695015794287f;    // (1-exp(-5))/19
    const float BETA  = 101.3613328f;            // (0.1*(1-exp(-5)))^-2
    float x  = expf(-dist);
    float u  = x - MU0;
    float a0 = expf(-BETA * u * u);
    float tt = expf(2.0f * BETA * DELTA * u);
    float s1 = expf(-BETA * DELTA * DELTA);
    float s2 = s1 * s1;
    float val = a0;
    float f = tt * s1;
    #pragma unroll
    for (int k = 0; k < 20; k++) {
        g_rbf[20 * pos + k] = val;
        val *= f;
        f *= s2;
    }
}

// ---------------- fp32 SGEMM 64x64 tiles, K=128: C = act(A@B + bias) ------
template<int ACT>
__global__ void __launch_bounds__(128)
gemm64x64(const float* __restrict__ A, const float* __restrict__ B,
          const float* __restrict__ bias, float* __restrict__ C,
          int M, int N) {
    __shared__ float As[32][68];
    __shared__ float Bs[32][68];
    int tid = threadIdx.x;
    int tx = tid & 15, ty = tid >> 4;
    int brow = blockIdx.x * 64;
    int bcol = blockIdx.y * 64;
    float acc[8][4];
    #pragma unroll
    for (int i = 0; i < 8; i++)
        #pragma unroll
        for (int j = 0; j < 4; j++) acc[i][j] = 0.f;

    for (int kt = 0; kt < 4; kt++) {
        #pragma unroll
        for (int r = 0; r < 16; r++) {
            int lin = tid + 128 * r;
            int m = lin >> 5, k = lin & 31;
            int gm = brow + m;
            As[k][m] = (gm < M) ? A[gm * 128 + kt * 32 + k] : 0.f;
        }
        #pragma unroll
        for (int r = 0; r < 16; r++) {
            int lin = tid + 128 * r;
            int k = lin >> 6, n = lin & 63;
            Bs[k][n] = B[(kt * 32 + k) * N + bcol + n];
        }
        __syncthreads();
        #pragma unroll
        for (int k = 0; k < 32; k++) {
            float4 a0 = *reinterpret_cast<const float4*>(&As[k][ty * 8]);
            float4 a1 = *reinterpret_cast<const float4*>(&As[k][ty * 8 + 4]);
            float4 b  = *reinterpret_cast<const float4*>(&Bs[k][tx * 4]);
            float av[8] = {a0.x, a0.y, a0.z, a0.w, a1.x, a1.y, a1.z, a1.w};
            float bv[4] = {b.x, b.y, b.z, b.w};
            #pragma unroll
            for (int i = 0; i < 8; i++)
                #pragma unroll
                for (int j = 0; j < 4; j++)
                    acc[i][j] += av[i] * bv[j];
        }
        __syncthreads();
    }
    float bv[4];
    #pragma unroll
    for (int j = 0; j < 4; j++) bv[j] = bias[bcol + tx * 4 + j];
    #pragma unroll
    for (int i = 0; i < 8; i++) {
        int row = brow + ty * 8 + i;
        if (row < M) {
            float o[4];
            #pragma unroll
            for (int j = 0; j < 4; j++) {
                float c = acc[i][j] + bv[j];
                if (ACT) c = c / (1.0f + expf(-c));   // silu
                o[j] = c;
            }
            *reinterpret_cast<float4*>(&C[row * N + bcol + tx * 4]) =
                make_float4(o[0], o[1], o[2], o[3]);
        }
    }
}

// ---------------- edge kernel: vectorized broadcasts, shuffle scatter -----
template<bool FIRST>
__global__ void __launch_bounds__(128)
edge_kernel(const float* __restrict__ phi, const float* __restrict__ v_in,
            float* __restrict__ s_acc, float* __restrict__ v_acc,
            const float* __restrict__ Wr, const float* __restrict__ brv) {
    __shared__ float rbf_s[32 * 20];          // 80B/edge, float4-aligned
    __shared__ float meta_s[32][8];           // ii, jj, env, ux, uy, uz, -, -
    int t = threadIdx.x;
    int sub = t & 3;

    // Wr columns for features {t, 128+t, 256+t} live in registers
    float wr[60];
    #pragma unroll
    for (int k = 0; k < 20; k++) {
        wr[k]      = Wr[k * 384 + t];
        wr[20 + k] = Wr[k * 384 + 128 + t];
        wr[40 + k] = Wr[k * 384 + 256 + t];
    }
    float br0 = brv[t], br1 = brv[128 + t], br2 = brv[256 + t];

    int count = g_count;
    int ntiles = (count + 31) >> 5;
    for (int tile = blockIdx.x; tile < ntiles; tile += gridDim.x) {
        int e0 = tile << 5;
        int emax = min(32, count - e0);
        if (t < 32 && t < emax) {
            meta_s[t][0] = __int_as_float(g_ei[e0 + t]);
            meta_s[t][1] = __int_as_float(g_ej[e0 + t]);
            meta_s[t][2] = g_env[e0 + t];
            meta_s[t][3] = g_ux[e0 + t];
            meta_s[t][4] = g_uy[e0 + t];
            meta_s[t][5] = g_uz[e0 + t];
        }
        {   // copy emax*20 floats as float4s (both sides 16B-aligned)
            int nv4 = emax * 5;
            const float4* src = reinterpret_cast<const float4*>(g_rbf + (size_t)e0 * 20);
            float4* dstv = reinterpret_cast<float4*>(rbf_s);
            for (int x = t; x < nv4; x += 128) dstv[x] = src[x];
        }
        __syncthreads();

        for (int e = 0; e < emax; e++) {
            float4 m0 = *reinterpret_cast<const float4*>(&meta_s[e][0]);
            float4 m1 = *reinterpret_cast<const float4*>(&meta_s[e][4]);
            int node = __float_as_int(m0.x);
            int j    = __float_as_int(m0.y);
            float env = m0.z, ux = m0.w, uy = m1.x, uz = m1.y;

            const float4* rb = reinterpret_cast<const float4*>(rbf_s + e * 20);
            float4 q0 = rb[0], q1 = rb[1], q2 = rb[2], q3 = rb[3], q4 = rb[4];
            float rv[20] = {q0.x, q0.y, q0.z, q0.w, q1.x, q1.y, q1.z, q1.w,
                            q2.x, q2.y, q2.z, q2.w, q3.x, q3.y, q3.z, q3.w,
                            q4.x, q4.y, q4.z, q4.w};
            float ws0 = br0, ws1 = br1, ws2 = br2;
            #pragma unroll
            for (int k = 0; k < 20; k++) {
                ws0 += rv[k] * wr[k];
                ws1 += rv[k] * wr[20 + k];
                ws2 += rv[k] * wr[40 + k];
            }
            const float* pj = phi + (size_t)j * 384;
            float r0 = pj[t]       * ws0 * env;          // ds
            float gv = pj[128 + t] * ws1 * env;
            float gu = pj[256 + t] * ws2 * env;
            float r1, r2, r3;
            if (FIRST) {
                r1 = gu * ux; r2 = gu * uy; r3 = gu * uz;
            } else {
                const float* vj = v_in + (size_t)j * 384;
                r1 = gu * ux + gv * vj[t];
                r2 = gu * uy + gv * vj[128 + t];
                r3 = gu * uz + gv * vj[256 + t];
            }

            // 4x4 transpose within lane groups of 4 (2-stage butterfly)
            float s01 = (sub & 1) ? r0 : r1;
            s01 = __shfl_xor_sync(0xffffffffu, s01, 1);
            if (sub & 1) r0 = s01; else r1 = s01;
            float s23 = (sub & 1) ? r2 : r3;
            s23 = __shfl_xor_sync(0xffffffffu, s23, 1);
            if (sub & 1) r2 = s23; else r3 = s23;
            float s02 = (sub & 2) ? r0 : r2;
            s02 = __shfl_xor_sync(0xffffffffu, s02, 2);
            if (sub & 2) r0 = s02; else r2 = s02;
            float s13 = (sub & 2) ? r1 : r3;
            s13 = __shfl_xor_sync(0xffffffffu, s13, 2);
            if (sub & 2) r1 = s13; else r3 = s13;
            // lane 4q+a now holds array a (a=0:ds, 1:vx, 2:vy, 3:vz)

            int fbase = t & ~3;
            float* dst = (sub == 0)
                ? (s_acc + node * 128 + fbase)
                : (v_acc + node * 384 + (sub - 1) * 128 + fbase);
            red4(dst, r0, r1, r2, r3);
        }
        __syncthreads();
    }
}

// ---------------- epilogue: SoA v -> interleaved (N,128,3) ----------------
__global__ void __launch_bounds__(128)
interleave_kernel(const float* __restrict__ v_soa, float* __restrict__ out) {
    __shared__ float sm[384];
    int i = blockIdx.x;
    int t = threadIdx.x;
    sm[t]       = v_soa[i * 384 + t];
    sm[128 + t] = v_soa[i * 384 + 128 + t];
    sm[256 + t] = v_soa[i * 384 + 256 + t];
    __syncthreads();
    #pragma unroll
    for (int r = 0; r < 3; r++) {
        int x = t + 128 * r;
        out[i * 384 + x] = sm[(x % 3) * 128 + x / 3];
    }
}

// ---------------- orchestration -------------------------------------------
extern "C" void kernel_launch(void* const* d_in, const int* in_sizes, int n_in,
                              void* d_out, int out_size) {
    (void)in_sizes; (void)n_in; (void)out_size;
    const float* xyz  = (const float*)d_in[0];
    const int*   nbr  = (const int*)d_in[1];
    const float* cg_s = (const float*)d_in[2];
    const float* W1   = (const float*)d_in[3];
    const float* b1   = (const float*)d_in[4];
    const float* W2   = (const float*)d_in[5];
    const float* b2   = (const float*)d_in[6];
    const float* Wr   = (const float*)d_in[7];
    const float* brr  = (const float*)d_in[8];
    float* s_out = (float*)d_out;                       // (N,128)
    float* v_out_final = s_out + (size_t)NN * 128;      // (N,128,3)

    void *p_count, *p_h, *p_phi, *p_va, *p_vb;
    cudaGetSymbolAddress(&p_count, g_count);
    cudaGetSymbolAddress(&p_h, g_h);
    cudaGetSymbolAddress(&p_phi, g_phi);
    cudaGetSymbolAddress(&p_va, g_va);
    cudaGetSymbolAddress(&p_vb, g_vb);

    size_t vbytes = (size_t)NN * 384 * sizeof(float);
    cudaMemsetAsync(p_count, 0, sizeof(int));
    cudaMemsetAsync(p_va, 0, vbytes);
    cudaMemcpyAsync(s_out, cg_s, (size_t)NN * 128 * sizeof(float),
                    cudaMemcpyDeviceToDevice);

    precompute_kernel<<<(NE + 127) / 128, 128>>>(xyz, nbr);

    dim3 g1((NN + 63) / 64, 2), g2((NN + 63) / 64, 6);

    // layer 0: v_in unused (zero), scatter into va (zeroed)
    gemm64x64<1><<<g1, 128>>>(s_out, W1, b1, (float*)p_h, NN, 128);
    gemm64x64<0><<<g2, 128>>>((const float*)p_h, W2, b2, (float*)p_phi, NN, 384);
    edge_kernel<true><<<1480, 128>>>((const float*)p_phi, nullptr,
                                     s_out, (float*)p_va, Wr, brr);
    // layer 1: read va, scatter into vb (= copy of va)
    gemm64x64<1><<<g1, 128>>>(s_out, W1 + 128 * 128, b1 + 128, (float*)p_h, NN, 128);
    gemm64x64<0><<<g2, 128>>>((const float*)p_h, W2 + 128 * 384, b2 + 384,
                              (float*)p_phi, NN, 384);
    cudaMemcpyAsync(p_vb, p_va, vbytes, cudaMemcpyDeviceToDevice);
    edge_kernel<false><<<1480, 128>>>((const float*)p_phi, (const float*)p_va,
                                      s_out, (float*)p_vb,
                                      Wr + 20 * 384, brr + 384);
    // layer 2: read vb, scatter into va (= copy of vb)
    gemm64x64<1><<<g1, 128>>>(s_out, W1 + 2 * 128 * 128, b1 + 2 * 128,
                              (float*)p_h, NN, 128);
    gemm64x64<0><<<g2, 128>>>((const float*)p_h, W2 + 2 * 128 * 384, b2 + 2 * 384,
                              (float*)p_phi, NN, 384);
    cudaMemcpyAsync(p_va, p_vb, vbytes, cudaMemcpyDeviceToDevice);
    edge_kernel<false><<<1480, 128>>>((const float*)p_phi, (const float*)p_vb,
                                      s_out, (float*)p_va,
                                      Wr + 2 * 20 * 384, brr + 2 * 384);

    interleave_kernel<<<NN, 128>>>((const float*)p_va, v_out_final);
}